// round 16
// baseline (speedup 1.0000x reference)
// THEORY (round 16): (1) NT=96 GEMM tile for pruned proj/fc2 (M<=7680):
// 480 CTAs -> 1 wave of 1.5x tiles (1.5 tile-times) vs 720 CTAs -> 2 waves
// (2.0) for NT=64; ~25% faster on those launches (~0.10 ms). (2) flash smem
// overlay: Qs region is dead after register hoist -> Ks reuses it, 55KB ->
// 36.9KB smem. (3) wsplit uint2 packed stores (coalesced 64B rows).
// Predict dur_us 5673 -> ~5530-5610, rel_err ~4.4e-6.
#include <cuda_runtime.h>
#include <cuda_fp16.h>
#include <stdint.h>
#include <stddef.h>
#include <math.h>

#define BATCH   64
#define CDIM    384
#define HEADS   6
#define MLPD    1536
#define LAYERS  12
#define NPATCH  196
#define MAXN    197
#define NCLS    100
#define EPSLN   1e-6f
#define SCALE   0.125f
#define ASTRIDE 224
#define WSCALE     64.f
#define INV_WSCALE (1.f/64.f)

#define SZ_PATCH (768*384)
#define SZ_QKV   (384*1152)
#define SZ_PROJ  (384*384)
#define SZ_FC1   (384*1536)
#define SZ_FC2   (1536*384)
#define OFF_PATCH 0
#define OFF_QKV   (SZ_PATCH)
#define OFF_PROJ  (OFF_QKV + 12*SZ_QKV)
#define OFF_FC1   (OFF_PROJ + 12*SZ_PROJ)
#define OFF_FC2   (OFF_FC1 + 12*SZ_FC1)
#define WTOTAL    (OFF_FC2 + 12*SZ_FC2)

__device__ float  g_h0[(size_t)BATCH * MAXN * CDIM];
__device__ float  g_h1[(size_t)BATCH * MAXN * CDIM];
__device__ float  g_pembed[(size_t)BATCH * NPATCH * CDIM];
__device__ int    g_idx[BATCH * NPATCH];
__device__ float  g_cls[(size_t)BATCH * HEADS * ASTRIDE];

__device__ __half g_wth[(size_t)WTOTAL];
__device__ __half g_wtl[(size_t)WTOTAL];
__device__ __half g_lnh[(size_t)BATCH * MAXN * CDIM];
__device__ __half g_lnl[(size_t)BATCH * MAXN * CDIM];
__device__ __half g_qkvh[(size_t)BATCH * MAXN * 1152];
__device__ __half g_qkvl[(size_t)BATCH * MAXN * 1152];
__device__ __half g_aoh[(size_t)BATCH * MAXN * CDIM];
__device__ __half g_aol[(size_t)BATCH * MAXN * CDIM];
__device__ __half g_mlph[(size_t)BATCH * MAXN * MLPD];
__device__ __half g_mlpl[(size_t)BATCH * MAXN * MLPD];
__device__ __half g_pxh[(size_t)BATCH * NPATCH * 768];
__device__ __half g_pxl[(size_t)BATCH * NPATCH * 768];

__device__ __forceinline__ void split_h(float v, __half& h, __half& l) {
    h = __float2half_rn(v);
    l = __float2half_rn(v - __half2float(h));
}

__device__ __forceinline__ void packsplit(float a, float b, unsigned& hi, unsigned& lo) {
    __half ah = __float2half_rn(a);
    __half al = __float2half_rn(a - __half2float(ah));
    __half bh = __float2half_rn(b);
    __half bl = __float2half_rn(b - __half2float(bh));
    hi = (unsigned)__half_as_ushort(ah) | ((unsigned)__half_as_ushort(bh) << 16);
    lo = (unsigned)__half_as_ushort(al) | ((unsigned)__half_as_ushort(bl) << 16);
}

__device__ __forceinline__ void mma16(float* c, const unsigned* a, const unsigned* b) {
    asm volatile(
        "mma.sync.aligned.m16n8k16.row.col.f32.f16.f16.f32 "
        "{%0,%1,%2,%3},{%4,%5,%6,%7},{%8,%9},{%0,%1,%2,%3};"
        : "+f"(c[0]), "+f"(c[1]), "+f"(c[2]), "+f"(c[3])
        : "r"(a[0]), "r"(a[1]), "r"(a[2]), "r"(a[3]), "r"(b[0]), "r"(b[1]));
}

__device__ __forceinline__ void ldmx4t(unsigned* r, unsigned addr) {
    asm volatile("ldmatrix.sync.aligned.m8n8.x4.trans.shared.b16 {%0,%1,%2,%3}, [%4];"
                 : "=r"(r[0]), "=r"(r[1]), "=r"(r[2]), "=r"(r[3]) : "r"(addr));
}

__device__ __forceinline__ unsigned cvta_s(const void* p) {
    unsigned a;
    asm("{ .reg .u64 t; cvta.to.shared.u64 t, %1; cvt.u32.u64 %0, t; }" : "=r"(a) : "l"(p));
    return a;
}

__device__ __forceinline__ void cp16(unsigned dst, const void* src, unsigned sz) {
    asm volatile("cp.async.cg.shared.global [%0], [%1], 16, %2;"
                 :: "r"(dst), "l"(src), "r"(sz) : "memory");
}
#define CP_COMMIT() asm volatile("cp.async.commit_group;" ::: "memory")
#define CP_WAIT0()  asm volatile("cp.async.wait_group 0;" ::: "memory")

// ------- fp16x3 GEMM, 64(M) x NT(N) x 32(K) tile, 128 thr, single-sync pipeline ----
// smem halves: A[p][s] at p*5120 + s*2560 (10240 total);
//              B[p][s] at 10240 + p*(2*NT*40) + s*(NT*40)
#define GEMM_SMEM(NT)  (20480 + 320 * (NT))

template<int NT>
__device__ __forceinline__ void gemm_issue(
    unsigned sb, const __half* Ah, const __half* Al,
    const __half* Bth, const __half* Btl,
    int M, int K, int m0, int n0, int t, int c) {
    int p = c & 1;
    int kb = c * 32;
#pragma unroll
    for (int s = 0; s < 2; s++) {
        const __half* asrc = s ? Al : Ah;
#pragma unroll
        for (int it = 0; it < 2; it++) {
            int idx = t + it * 128;
            int row = idx >> 2, c4 = idx & 3;
            int gm = m0 + row;
            int gmc = (gm < M) ? gm : (M - 1);
            const __half* src = asrc + (size_t)gmc * K + kb + 8 * c4;
            unsigned dst = sb + (unsigned)(p * 5120 + s * 2560 + row * 40 + 8 * c4) * 2u;
            cp16(dst, src, (gm < M) ? 16u : 0u);
        }
        const __half* bsrc = s ? Btl : Bth;
#pragma unroll
        for (int it = 0; it < NT / 32; it++) {
            int idx = t + it * 128;
            int brow = idx >> 2, bc4 = idx & 3;
            const __half* srcb = bsrc + (size_t)(n0 + brow) * K + kb + 8 * bc4;
            unsigned dstb = sb + (unsigned)(10240 + p * (2 * NT * 40) + s * (NT * 40)
                                            + brow * 40 + 8 * bc4) * 2u;
            cp16(dstb, srcb, 16u);
        }
    }
    CP_COMMIT();
}

template<int KT, int NT, int EPI, bool OF32, bool OHALF>
__global__ __launch_bounds__(128, 4)
void gemm_fp16(const __half* __restrict__ Ah, const __half* __restrict__ Al,
               const __half* __restrict__ Bth, const __half* __restrict__ Btl,
               const float* __restrict__ bias, const float* __restrict__ res,
               float* __restrict__ C32, __half* __restrict__ Ch, __half* __restrict__ Cl,
               int M, int Nout, float oscale) {
    extern __shared__ __half smp[];
    unsigned sb = cvta_s(smp);
    int t = threadIdx.x, lane = t & 31, wid = t >> 5;
    int g = lane >> 2, q = lane & 3;
    int wm = wid >> 1, wn = wid & 1;
    int m0 = blockIdx.y * 64, n0 = blockIdx.x * NT;
    const int TN = NT / 16;
    float acc[2][TN][4] = {};
    const int nch = KT >> 5;

    gemm_issue<NT>(sb, Ah, Al, Bth, Btl, M, KT, m0, n0, t, 0);
#pragma unroll 2
    for (int c = 0; c < nch; c++) {
        CP_WAIT0();
        __syncthreads();
        if (c + 1 < nch) gemm_issue<NT>(sb, Ah, Al, Bth, Btl, M, KT, m0, n0, t, c + 1);
        int p = c & 1;
        const __half* Ab = smp + p * 5120;
        const __half* Bb = smp + 10240 + p * (2 * NT * 40);
#pragma unroll
        for (int ks = 0; ks < 2; ks++) {
            int kb = ks * 16;
            unsigned aH[2][4], aL[2][4];
#pragma unroll
            for (int tm = 0; tm < 2; tm++) {
                int r0 = wm * 32 + tm * 16;
                const __half* a0 = Ab + (r0 + g) * 40;
                const __half* a8 = Ab + (r0 + g + 8) * 40;
                aH[tm][0] = *(const unsigned*)(a0 + kb + 2 * q);
                aH[tm][1] = *(const unsigned*)(a8 + kb + 2 * q);
                aH[tm][2] = *(const unsigned*)(a0 + kb + 2 * q + 8);
                aH[tm][3] = *(const unsigned*)(a8 + kb + 2 * q + 8);
                const __half* l0 = a0 + 2560;
                const __half* l8 = a8 + 2560;
                aL[tm][0] = *(const unsigned*)(l0 + kb + 2 * q);
                aL[tm][1] = *(const unsigned*)(l8 + kb + 2 * q);
                aL[tm][2] = *(const unsigned*)(l0 + kb + 2 * q + 8);
                aL[tm][3] = *(const unsigned*)(l8 + kb + 2 * q + 8);
            }
            unsigned bH[TN][2], bL[TN][2];
#pragma unroll
            for (int tn = 0; tn < TN; tn++) {
                int n = wn * (NT / 2) + tn * 8 + g;
                const __half* b0 = Bb + n * 40;
                bH[tn][0] = *(const unsigned*)(b0 + kb + 2 * q);
                bH[tn][1] = *(const unsigned*)(b0 + kb + 2 * q + 8);
                const __half* bl = b0 + NT * 40;
                bL[tn][0] = *(const unsigned*)(bl + kb + 2 * q);
                bL[tn][1] = *(const unsigned*)(bl + kb + 2 * q + 8);
            }
#pragma unroll
            for (int tm = 0; tm < 2; tm++)
#pragma unroll
                for (int tn = 0; tn < TN; tn++) {
                    mma16(acc[tm][tn], aH[tm], bH[tn]);
                    mma16(acc[tm][tn], aH[tm], bL[tn]);
                    mma16(acc[tm][tn], aL[tm], bH[tn]);
                }
        }
    }

#pragma unroll
    for (int tm = 0; tm < 2; tm++) {
#pragma unroll
        for (int tn = 0; tn < TN; tn++) {
            int col = n0 + wn * (NT / 2) + tn * 8 + 2 * q;
            int r0 = m0 + wm * 32 + tm * 16;
            float2 bv = *(const float2*)&bias[col];
#pragma unroll
            for (int hf = 0; hf < 2; hf++) {
                int gm = r0 + g + 8 * hf;
                if (gm >= M) continue;
                float v0 = acc[tm][tn][hf * 2]     * oscale + bv.x;
                float v1 = acc[tm][tn][hf * 2 + 1] * oscale + bv.y;
                if (EPI == 1) {
                    float2 rv = *(const float2*)&res[(size_t)gm * Nout + col];
                    v0 += rv.x; v1 += rv.y;
                }
                if (EPI == 2) {
                    v0 = 0.5f * v0 * (1.f + erff(v0 * 0.70710678118654752f));
                    v1 = 0.5f * v1 * (1.f + erff(v1 * 0.70710678118654752f));
                }
                if (OF32) *(float2*)&C32[(size_t)gm * Nout + col] = make_float2(v0, v1);
                if (OHALF) {
                    unsigned ph2, pl2;
                    packsplit(v0, v1, ph2, pl2);
                    *(unsigned*)&Ch[(size_t)gm * Nout + col] = ph2;
                    *(unsigned*)&Cl[(size_t)gm * Nout + col] = pl2;
                }
            }
        }
    }
}

// ---------------- weight transpose + split (packed uint2 stores) ----------------
__global__ void wsplit_kernel(const float* __restrict__ W, size_t in_lstride,
                              __half* __restrict__ oh, __half* __restrict__ ol,
                              size_t out_lstride, int K, int N) {
    __shared__ float tile[32][33];
    int k0 = blockIdx.x * 32, n0 = blockIdx.y * 32;
    const float* Wl = W + (size_t)blockIdx.z * in_lstride;
    __half* ohl = oh + (size_t)blockIdx.z * out_lstride;
    __half* oll = ol + (size_t)blockIdx.z * out_lstride;
    int tx = threadIdx.x, ty = threadIdx.y;
#pragma unroll
    for (int i = 0; i < 4; i++)
        tile[ty + 8 * i][tx] = Wl[(size_t)(k0 + ty + 8 * i) * N + n0 + tx];
    __syncthreads();
    int t = ty * 32 + tx;
    int nl = t >> 3, kq = t & 7;
    float v0 = tile[4 * kq][nl]     * WSCALE;
    float v1 = tile[4 * kq + 1][nl] * WSCALE;
    float v2 = tile[4 * kq + 2][nl] * WSCALE;
    float v3 = tile[4 * kq + 3][nl] * WSCALE;
    unsigned h01, l01, h23, l23;
    packsplit(v0, v1, h01, l01);
    packsplit(v2, v3, h23, l23);
    size_t o = (size_t)(n0 + nl) * K + k0 + 4 * kq;
    *(uint2*)&ohl[o] = make_uint2(h01, h23);
    *(uint2*)&oll[o] = make_uint2(l01, l23);
}

// ---------------- patchify + split ----------------
__global__ void patchify_kernel(const float* __restrict__ x,
                                __half* __restrict__ ph, __half* __restrict__ pl) {
    int i = blockIdx.x * 256 + threadIdx.x;
    const int TOT = BATCH * NPATCH * 768;
    if (i >= TOT) return;
    int k  = i % 768;
    int tt = (i / 768) % NPATCH;
    int b  = i / (768 * NPATCH);
    int ch = k >> 8, py = (k >> 4) & 15, px = k & 15;
    int gy = tt / 14, gx = tt % 14;
    float v = x[(((size_t)b * 3 + ch) * 224 + gy * 16 + py) * 224 + gx * 16 + px];
    split_h(v, ph[i], pl[i]);
}

// ---------------- assemble ----------------
__global__ void assemble_kernel(const float* __restrict__ pe, const float* __restrict__ cls,
                                const float* __restrict__ pos, float* __restrict__ h) {
    int i = blockIdx.x * 256 + threadIdx.x;
    const int TOT = BATCH * MAXN * CDIM;
    if (i >= TOT) return;
    int c = i % CDIM;
    int r = (i / CDIM) % MAXN;
    int b = i / (CDIM * MAXN);
    float v = (r == 0) ? cls[c] : pe[((size_t)b * NPATCH + (r - 1)) * CDIM + c];
    h[i] = v + pos[r * CDIM + c];
}

// ---------------- LayerNorm: warp-per-row ----------------
__global__ __launch_bounds__(128)
void ln_kernel(const float* __restrict__ x, const float* __restrict__ g,
               const float* __restrict__ bb, __half* __restrict__ yh, __half* __restrict__ yl,
               int rows) {
    int row = blockIdx.x * 4 + (threadIdx.x >> 5);
    if (row >= rows) return;
    int lane = threadIdx.x & 31;
    const float4* xr = (const float4*)(x + (size_t)row * CDIM);
    float4 v[3];
    float s = 0.f, s2 = 0.f;
#pragma unroll
    for (int l = 0; l < 3; l++) {
        v[l] = xr[lane + 32 * l];
        s  += v[l].x + v[l].y + v[l].z + v[l].w;
        s2 += v[l].x * v[l].x + v[l].y * v[l].y + v[l].z * v[l].z + v[l].w * v[l].w;
    }
#pragma unroll
    for (int o = 16; o; o >>= 1) {
        s  += __shfl_xor_sync(~0u, s, o);
        s2 += __shfl_xor_sync(~0u, s2, o);
    }
    float mean = s * (1.f / CDIM);
    float var  = s2 * (1.f / CDIM) - mean * mean;
    float r = rsqrtf(var + EPSLN);
#pragma unroll
    for (int l = 0; l < 3; l++) {
        int c4 = lane + 32 * l;
        float4 gv = *(const float4*)(g + 4 * c4);
        float4 bv = *(const float4*)(bb + 4 * c4);
        float o0 = (v[l].x - mean) * r * gv.x + bv.x;
        float o1 = (v[l].y - mean) * r * gv.y + bv.y;
        float o2 = (v[l].z - mean) * r * gv.z + bv.z;
        float o3 = (v[l].w - mean) * r * gv.w + bv.w;
        unsigned h01, l01, h23, l23;
        packsplit(o0, o1, h01, l01);
        packsplit(o2, o3, h23, l23);
        *(uint2*)&yh[(size_t)row * CDIM + 4 * c4] = make_uint2(h01, h23);
        *(uint2*)&yl[(size_t)row * CDIM + 4 * c4] = make_uint2(l01, l23);
    }
}

// ---------------- fused flash attention (smem overlay: Ks reuses Qs) ----------------
#define FLASH_SMEM 36864

__global__ __launch_bounds__(128)
void flash_attn(const __half* __restrict__ qkvh, const __half* __restrict__ qkvl,
                __half* __restrict__ aoh, __half* __restrict__ aol,
                float* __restrict__ clslog, int N) {
    extern __shared__ __half fsm[];
    __half* Qs = fsm;            // prologue only
    __half* Ks = fsm;            // overlays Qs after fragment hoist
    __half* Vs = fsm + 9216;
    int bh = blockIdx.y;
    int b = bh / HEADS, hh = bh % HEADS;
    int i0 = blockIdx.x * 64;
    int t = threadIdx.x, lane = t & 31, wid = t >> 5;
    int g = lane >> 2, q = lane & 3;
    const uint4 z4 = make_uint4(0, 0, 0, 0);
    unsigned vs_addr = cvta_s(fsm) + 9216u * 2u;

#pragma unroll
    for (int s = 0; s < 2; s++) {
        const __half* src = s ? qkvl : qkvh;
#pragma unroll
        for (int it = 0; it < 4; it++) {
            int idx = t + it * 128;
            int row = idx >> 3, c = idx & 7;
            int gi = i0 + row;
            uint4 v = z4;
            if (gi < N) v = *(const uint4*)&src[((size_t)b * N + gi) * 1152 + hh * 64 + 8 * c];
            *(uint4*)&Qs[s * 4608 + row * 72 + 8 * c] = v;
        }
    }
    __syncthreads();

    unsigned qH[4][4], qL[4][4];
#pragma unroll
    for (int ks = 0; ks < 4; ks++) {
        int kb = ks * 16;
        const __half* a0 = Qs + (wid * 16 + g) * 72;
        const __half* a8 = Qs + (wid * 16 + g + 8) * 72;
        qH[ks][0] = *(const unsigned*)(a0 + kb + 2 * q);
        qH[ks][1] = *(const unsigned*)(a8 + kb + 2 * q);
        qH[ks][2] = *(const unsigned*)(a0 + kb + 2 * q + 8);
        qH[ks][3] = *(const unsigned*)(a8 + kb + 2 * q + 8);
        qL[ks][0] = *(const unsigned*)(a0 + 4608 + kb + 2 * q);
        qL[ks][1] = *(const unsigned*)(a8 + 4608 + kb + 2 * q);
        qL[ks][2] = *(const unsigned*)(a0 + 4608 + kb + 2 * q + 8);
        qL[ks][3] = *(const unsigned*)(a8 + 4608 + kb + 2 * q + 8);
    }

    float m_lo = -1e30f, m_hi = -1e30f, s_lo = 0.f, s_hi = 0.f;
    float acc_o[8][4] = {};
    int ntj = (N + 63) >> 6;

    unsigned vrow_in_tile = (unsigned)(lane & 15);
    unsigned vcol8 = (lane & 16) ? 8u : 0u;

    for (int jt = 0; jt < ntj; jt++) {
        int j0 = jt * 64;
        int tnm = (N - j0 + 7) >> 3;  if (tnm > 8) tnm = 8;
        int ksm = (N - j0 + 15) >> 4; if (ksm > 4) ksm = 4;
        __syncthreads();
#pragma unroll
        for (int s = 0; s < 2; s++) {
            const __half* src = s ? qkvl : qkvh;
#pragma unroll
            for (int it = 0; it < 4; it++) {
                int idx = t + it * 128;
                int row = idx >> 3, c = idx & 7;
                int gj = j0 + row;
                uint4 vk = z4, vv = z4;
                if (gj < N) {
                    size_t base = ((size_t)b * N + gj) * 1152 + hh * 64 + 8 * c;
                    vk = *(const uint4*)&src[base + 384];
                    vv = *(const uint4*)&src[base + 768];
                }
                *(uint4*)&Ks[s * 4608 + row * 72 + 8 * c] = vk;
                *(uint4*)&Vs[s * 4608 + row * 72 + 8 * c] = vv;
            }
        }
        __syncthreads();

        float sa[8][4] = {};
#pragma unroll
        for (int ks = 0; ks < 4; ks++) {
            int kb = ks * 16;
            for (int tn = 0; tn < tnm; tn++) {
                unsigned bHf[2], bLf[2];
                const __half* b0 = Ks + (tn * 8 + g) * 72;
                bHf[0] = *(const unsigned*)(b0 + kb + 2 * q);
                bHf[1] = *(const unsigned*)(b0 + kb + 2 * q + 8);
                bLf[0] = *(const unsigned*)(b0 + 4608 + kb + 2 * q);
                bLf[1] = *(const unsigned*)(b0 + 4608 + kb + 2 * q + 8);
                mma16(sa[tn], qH[ks], bHf);
                mma16(sa[tn], qH[ks], bLf);
                mma16(sa[tn], qL[ks], bHf);
            }
        }

#pragma unroll
        for (int tn = 0; tn < 8; tn++) {
#pragma unroll
            for (int r = 0; r < 4; r++) {
                int col = j0 + tn * 8 + 2 * q + (r & 1);
                float v = sa[tn][r] * SCALE;
                sa[tn][r] = (col < N) ? v : -1e30f;
            }
        }
        if (blockIdx.x == 0 && wid == 0 && g == 0) {
#pragma unroll
            for (int tn = 0; tn < 8; tn++) {
#pragma unroll
                for (int r = 0; r < 2; r++) {
                    int col = j0 + tn * 8 + 2 * q + r;
                    if (col < ASTRIDE) clslog[(size_t)bh * ASTRIDE + col] = sa[tn][r];
                }
            }
        }

        float mt_lo = -1e30f, mt_hi = -1e30f;
#pragma unroll
        for (int tn = 0; tn < 8; tn++) {
            mt_lo = fmaxf(mt_lo, fmaxf(sa[tn][0], sa[tn][1]));
            mt_hi = fmaxf(mt_hi, fmaxf(sa[tn][2], sa[tn][3]));
        }
        mt_lo = fmaxf(mt_lo, __shfl_xor_sync(~0u, mt_lo, 1));
        mt_lo = fmaxf(mt_lo, __shfl_xor_sync(~0u, mt_lo, 2));
        mt_hi = fmaxf(mt_hi, __shfl_xor_sync(~0u, mt_hi, 1));
        mt_hi = fmaxf(mt_hi, __shfl_xor_sync(~0u, mt_hi, 2));
        float mn_lo = fmaxf(m_lo, mt_lo), mn_hi = fmaxf(m_hi, mt_hi);
        float al_lo = expf(m_lo - mn_lo), al_hi = expf(m_hi - mn_hi);
        m_lo = mn_lo; m_hi = mn_hi;
        float ts_lo = 0.f, ts_hi = 0.f;
#pragma unroll
        for (int tn = 0; tn < 8; tn++) {
            sa[tn][0] = expf(sa[tn][0] - m_lo) * 256.f;
            sa[tn][1] = expf(sa[tn][1] - m_lo) * 256.f;
            sa[tn][2] = expf(sa[tn][2] - m_hi) * 256.f;
            sa[tn][3] = expf(sa[tn][3] - m_hi) * 256.f;
            ts_lo += sa[tn][0] + sa[tn][1];
            ts_hi += sa[tn][2] + sa[tn][3];
        }
        ts_lo += __shfl_xor_sync(~0u, ts_lo, 1);
        ts_lo += __shfl_xor_sync(~0u, ts_lo, 2);
        ts_hi += __shfl_xor_sync(~0u, ts_hi, 1);
        ts_hi += __shfl_xor_sync(~0u, ts_hi, 2);
        s_lo = s_lo * al_lo + ts_lo;
        s_hi = s_hi * al_hi + ts_hi;
#pragma unroll
        for (int tn = 0; tn < 8; tn++) {
            acc_o[tn][0] *= al_lo; acc_o[tn][1] *= al_lo;
            acc_o[tn][2] *= al_hi; acc_o[tn][3] *= al_hi;
        }

        for (int ks = 0; ks < ksm; ks++) {
            unsigned aH[4], aL[4];
            packsplit(sa[2 * ks][0],     sa[2 * ks][1],     aH[0], aL[0]);
            packsplit(sa[2 * ks][2],     sa[2 * ks][3],     aH[1], aL[1]);
            packsplit(sa[2 * ks + 1][0], sa[2 * ks + 1][1], aH[2], aL[2]);
            packsplit(sa[2 * ks + 1][2], sa[2 * ks + 1][3], aH[3], aL[3]);
            unsigned rowbase = (unsigned)(ks * 16) + vrow_in_tile;
#pragma unroll
            for (int ng = 0; ng < 4; ng++) {
                unsigned addrH = vs_addr + (rowbase * 72u + (unsigned)(ng * 16) + vcol8) * 2u;
                unsigned bh4[4], bl4[4];
                ldmx4t(bh4, addrH);
                ldmx4t(bl4, addrH + 4608u * 2u);
                mma16(acc_o[2 * ng],     aH, &bh4[0]);
                mma16(acc_o[2 * ng],     aH, &bl4[0]);
                mma16(acc_o[2 * ng],     aL, &bh4[0]);
                mma16(acc_o[2 * ng + 1], aH, &bh4[2]);
                mma16(acc_o[2 * ng + 1], aH, &bl4[2]);
                mma16(acc_o[2 * ng + 1], aL, &bh4[2]);
            }
        }
    }

    float inv_lo = 1.f / fmaxf(s_lo, 1e-30f);
    float inv_hi = 1.f / fmaxf(s_hi, 1e-30f);
#pragma unroll
    for (int tn = 0; tn < 8; tn++) {
#pragma unroll
        for (int r = 0; r < 4; r++) {
            int gi = i0 + wid * 16 + g + ((r >= 2) ? 8 : 0);
            if (gi >= N) continue;
            int d = tn * 8 + 2 * q + (r & 1);
            float v = acc_o[tn][r] * ((r < 2) ? inv_lo : inv_hi);
            __half hh2, ll2;
            split_h(v, hh2, ll2);
            size_t oo = ((size_t)b * N + gi) * CDIM + hh * 64 + d;
            aoh[oo] = hh2;
            aol[oo] = ll2;
        }
    }
}

// ---------------- merged prune kernel ----------------
__global__ __launch_bounds__(256)
void prune_kernel(const float* __restrict__ cls, int* __restrict__ idxout, int N, int keep) {
    int b = blockIdx.x;
    int t = threadIdx.x;
    __shared__ float sc[256];
    __shared__ float red[8];
    int Ntok = N - 1;
    sc[t] = 0.f;
    __syncthreads();
    for (int hh = 0; hh < HEADS; hh++) {
        const float* r = cls + (size_t)(b * HEADS + hh) * ASTRIDE;
        float mx = -1e30f;
        for (int j = t; j < N; j += 256) mx = fmaxf(mx, r[j]);
#pragma unroll
        for (int o = 16; o; o >>= 1) mx = fmaxf(mx, __shfl_xor_sync(~0u, mx, o));
        if ((t & 31) == 0) red[t >> 5] = mx;
        __syncthreads();
        mx = red[0];
#pragma unroll
        for (int w = 1; w < 8; w++) mx = fmaxf(mx, red[w]);
        __syncthreads();
        float sum = 0.f;
        for (int j = t; j < N; j += 256) sum += expf(r[j] - mx);
#pragma unroll
        for (int o = 16; o; o >>= 1) sum += __shfl_xor_sync(~0u, sum, o);
        if ((t & 31) == 0) red[t >> 5] = sum;
        __syncthreads();
        sum = 0.f;
#pragma unroll
        for (int w = 0; w < 8; w++) sum += red[w];
        float inv = 1.f / sum;
        for (int j = t; j < Ntok; j += 256) sc[j] += expf(r[1 + j] - mx) * inv;
        __syncthreads();
    }
    if (t < Ntok) {
        float mine = sc[t];
        int rk = 0;
        for (int j = 0; j < Ntok; j++)
            rk += (sc[j] > mine) || (sc[j] == mine && j < t);
        if (rk < keep) idxout[b * keep + rk] = t;
    }
}

__global__ void gather_kernel(const float* __restrict__ src, float* __restrict__ dst,
                              const int* __restrict__ idx, int N, int keep) {
    int newN = keep + 1;
    size_t TOT = (size_t)BATCH * newN * CDIM;
    size_t i = (size_t)blockIdx.x * 256 + threadIdx.x;
    if (i >= TOT) return;
    int c = i % CDIM;
    int r = (i / CDIM) % newN;
    int b = i / ((size_t)CDIM * newN);
    int sr = (r == 0) ? 0 : 1 + idx[b * keep + r - 1];
    dst[i] = src[((size_t)b * N + sr) * CDIM + c];
}

// ---------------- fused final LN + head ----------------
__global__ __launch_bounds__(128)
void head_kernel(const float* __restrict__ h, const float* __restrict__ g,
                 const float* __restrict__ bb, const float* __restrict__ W,
                 const float* __restrict__ wb, float* __restrict__ out, int N) {
    int b = blockIdx.x;
    const float* xr = h + (size_t)(b * N) * CDIM;
    __shared__ float sm[CDIM];
    int t = threadIdx.x;
    float v[3];
    float s = 0.f, s2 = 0.f;
#pragma unroll
    for (int l = 0; l < 3; l++) { v[l] = xr[t + 128 * l]; s += v[l]; s2 += v[l] * v[l]; }
#pragma unroll
    for (int o = 16; o; o >>= 1) {
        s  += __shfl_xor_sync(~0u, s, o);
        s2 += __shfl_xor_sync(~0u, s2, o);
    }
    __shared__ float ws[4], ws2[4];
    if ((t & 31) == 0) { ws[t >> 5] = s; ws2[t >> 5] = s2; }
    __syncthreads();
    s  = ws[0] + ws[1] + ws[2] + ws[3];
    s2 = ws2[0] + ws2[1] + ws2[2] + ws2[3];
    float mean = s * (1.f / CDIM);
    float var  = s2 * (1.f / CDIM) - mean * mean;
    float r = rsqrtf(var + EPSLN);
#pragma unroll
    for (int l = 0; l < 3; l++) {
        int c = t + 128 * l;
        sm[c] = (v[l] - mean) * r * g[c] + bb[c];
    }
    __syncthreads();
    if (t < NCLS) {
        float acc = wb[t];
        for (int k = 0; k < CDIM; k++)
            acc += sm[k] * W[k * NCLS + t];
        out[b * NCLS + t] = acc;
    }
}

// ---------------- launch ----------------
extern "C" void kernel_launch(void* const* d_in, const int* in_sizes, int n_in,
                              void* d_out, int out_size) {
    const float* x        = (const float*)d_in[0];
    const float* patch_w  = (const float*)d_in[1];
    const float* patch_b  = (const float*)d_in[2];
    const float* cls_tok  = (const float*)d_in[3];
    const float* pos_emb  = (const float*)d_in[4];
    const float* ln1_g    = (const float*)d_in[5];
    const float* ln1_b    = (const float*)d_in[6];
    const float* qkv_w    = (const float*)d_in[7];
    const float* qkv_b    = (const float*)d_in[8];
    const float* proj_w   = (const float*)d_in[9];
    const float* proj_b   = (const float*)d_in[10];
    const float* ln2_g    = (const float*)d_in[11];
    const float* ln2_b    = (const float*)d_in[12];
    const float* fc1_w    = (const float*)d_in[13];
    const float* fc1_b    = (const float*)d_in[14];
    const float* fc2_w    = (const float*)d_in[15];
    const float* fc2_b    = (const float*)d_in[16];
    const float* norm_g   = (const float*)d_in[17];
    const float* norm_b   = (const float*)d_in[18];
    const float* head_w   = (const float*)d_in[19];
    const float* head_b   = (const float*)d_in[20];

    float *h[2], *pembed, *clsb;
    int* idxb;
    __half *wth, *wtl, *lnh, *lnl, *qkvh, *qkvl, *aoh, *aol, *mlph, *mlpl, *pxh, *pxl;
    cudaGetSymbolAddress((void**)&h[0], g_h0);
    cudaGetSymbolAddress((void**)&h[1], g_h1);
    cudaGetSymbolAddress((void**)&pembed, g_pembed);
    cudaGetSymbolAddress((void**)&idxb, g_idx);
    cudaGetSymbolAddress((void**)&clsb, g_cls);
    cudaGetSymbolAddress((void**)&wth, g_wth);
    cudaGetSymbolAddress((void**)&wtl, g_wtl);
    cudaGetSymbolAddress((void**)&lnh, g_lnh);
    cudaGetSymbolAddress((void**)&lnl, g_lnl);
    cudaGetSymbolAddress((void**)&qkvh, g_qkvh);
    cudaGetSymbolAddress((void**)&qkvl, g_qkvl);
    cudaGetSymbolAddress((void**)&aoh, g_aoh);
    cudaGetSymbolAddress((void**)&aol, g_aol);
    cudaGetSymbolAddress((void**)&mlph, g_mlph);
    cudaGetSymbolAddress((void**)&mlpl, g_mlpl);
    cudaGetSymbolAddress((void**)&pxh, g_pxh);
    cudaGetSymbolAddress((void**)&pxl, g_pxl);

    cudaFuncSetAttribute(gemm_fp16<768,  64, 0, true,  false>, cudaFuncAttributeMaxDynamicSharedMemorySize, GEMM_SMEM(64));
    cudaFuncSetAttribute(gemm_fp16<384,  64, 0, false, true >, cudaFuncAttributeMaxDynamicSharedMemorySize, GEMM_SMEM(64));
    cudaFuncSetAttribute(gemm_fp16<384,  64, 1, true,  false>, cudaFuncAttributeMaxDynamicSharedMemorySize, GEMM_SMEM(64));
    cudaFuncSetAttribute(gemm_fp16<384,  64, 2, false, true >, cudaFuncAttributeMaxDynamicSharedMemorySize, GEMM_SMEM(64));
    cudaFuncSetAttribute(gemm_fp16<1536, 64, 1, true,  false>, cudaFuncAttributeMaxDynamicSharedMemorySize, GEMM_SMEM(64));
    cudaFuncSetAttribute(gemm_fp16<384,  96, 1, true,  false>, cudaFuncAttributeMaxDynamicSharedMemorySize, GEMM_SMEM(96));
    cudaFuncSetAttribute(gemm_fp16<1536, 96, 1, true,  false>, cudaFuncAttributeMaxDynamicSharedMemorySize, GEMM_SMEM(96));
    cudaFuncSetAttribute(flash_attn, cudaFuncAttributeMaxDynamicSharedMemorySize, FLASH_SMEM);

    {
        dim3 blk(32, 8);
        wsplit_kernel<<<dim3(768 / 32, 384 / 32, 1), blk>>>(patch_w, 0, wth + OFF_PATCH, wtl + OFF_PATCH, 0, 768, 384);
        wsplit_kernel<<<dim3(384 / 32, 1152 / 32, 12), blk>>>(qkv_w, (size_t)384 * 1152, wth + OFF_QKV, wtl + OFF_QKV, SZ_QKV, 384, 1152);
        wsplit_kernel<<<dim3(384 / 32, 384 / 32, 12), blk>>>(proj_w, (size_t)384 * 384, wth + OFF_PROJ, wtl + OFF_PROJ, SZ_PROJ, 384, 384);
        wsplit_kernel<<<dim3(384 / 32, 1536 / 32, 12), blk>>>(fc1_w, (size_t)384 * 1536, wth + OFF_FC1, wtl + OFF_FC1, SZ_FC1, 384, 1536);
        wsplit_kernel<<<dim3(1536 / 32, 384 / 32, 12), blk>>>(fc2_w, (size_t)1536 * 384, wth + OFF_FC2, wtl + OFF_FC2, SZ_FC2, 1536, 384);
    }

    {
        int tot = BATCH * NPATCH * 768;
        patchify_kernel<<<(tot + 255) / 256, 256>>>(x, pxh, pxl);
        int M = BATCH * NPATCH;
        gemm_fp16<768, 64, 0, true, false><<<dim3(CDIM / 64, (M + 63) / 64), 128, GEMM_SMEM(64)>>>(
            pxh, pxl, wth + OFF_PATCH, wtl + OFF_PATCH, patch_b, nullptr,
            pembed, nullptr, nullptr, M, CDIM, INV_WSCALE);
        int tot2 = BATCH * MAXN * CDIM;
        assemble_kernel<<<(tot2 + 255) / 256, 256>>>(pembed, cls_tok, pos_emb, h[0]);
    }

    int cur = 0;
    int N = MAXN;
    for (int l = 0; l < LAYERS; l++) {
        int M = BATCH * N;
        int mt = (M + 63) / 64;
        bool use96 = (M <= 7680);
        ln_kernel<<<(M + 3) / 4, 128>>>(h[cur], ln1_g + l * CDIM, ln1_b + l * CDIM, lnh, lnl, M);
        gemm_fp16<384, 64, 0, false, true><<<dim3(1152 / 64, mt), 128, GEMM_SMEM(64)>>>(
            lnh, lnl, wth + OFF_QKV + (size_t)l * SZ_QKV, wtl + OFF_QKV + (size_t)l * SZ_QKV,
            qkv_b + l * 1152, nullptr, nullptr, qkvh, qkvl, M, 1152, INV_WSCALE);
        int nt = (N + 63) / 64;
        flash_attn<<<dim3(nt, BATCH * HEADS), 128, FLASH_SMEM>>>(qkvh, qkvl, aoh, aol, clsb, N);
        if (use96) {
            gemm_fp16<384, 96, 1, true, false><<<dim3(CDIM / 96, mt), 128, GEMM_SMEM(96)>>>(
                aoh, aol, wth + OFF_PROJ + (size_t)l * SZ_PROJ, wtl + OFF_PROJ + (size_t)l * SZ_PROJ,
                proj_b + l * CDIM, h[cur], h[cur], nullptr, nullptr, M, CDIM, INV_WSCALE);
        } else {
            gemm_fp16<384, 64, 1, true, false><<<dim3(CDIM / 64, mt), 128, GEMM_SMEM(64)>>>(
                aoh, aol, wth + OFF_PROJ + (size_t)l * SZ_PROJ, wtl + OFF_PROJ + (size_t)l * SZ_PROJ,
                proj_b + l * CDIM, h[cur], h[cur], nullptr, nullptr, M, CDIM, INV_WSCALE);
        }
        if (l == 2 || l == 4 || l == 6) {
            int keep = (l == 2) ? 176 : (l == 4) ? 149 : 119;
            prune_kernel<<<BATCH, 256>>>(clsb, idxb, N, keep);
            int newN = keep + 1;
            size_t tot = (size_t)BATCH * newN * CDIM;
            gather_kernel<<<(int)((tot + 255) / 256), 256>>>(h[cur], h[1 - cur], idxb, N, keep);
            cur ^= 1;
            N = newN;
            M = BATCH * N;
            mt = (M + 63) / 64;
            use96 = (M <= 7680);
        }
        ln_kernel<<<(M + 3) / 4, 128>>>(h[cur], ln2_g + l * CDIM, ln2_b + l * CDIM, lnh, lnl, M);
        gemm_fp16<384, 64, 2, false, true><<<dim3(MLPD / 64, mt), 128, GEMM_SMEM(64)>>>(
            lnh, lnl, wth + OFF_FC1 + (size_t)l * SZ_FC1, wtl + OFF_FC1 + (size_t)l * SZ_FC1,
            fc1_b + l * MLPD, nullptr, nullptr, mlph, mlpl, M, MLPD, INV_WSCALE);
        if (use96) {
            gemm_fp16<1536, 96, 1, true, false><<<dim3(CDIM / 96, mt), 128, GEMM_SMEM(96)>>>(
                mlph, mlpl, wth + OFF_FC2 + (size_t)l * SZ_FC2, wtl + OFF_FC2 + (size_t)l * SZ_FC2,
                fc2_b + l * CDIM, h[cur], h[cur], nullptr, nullptr, M, CDIM, INV_WSCALE);
        } else {
            gemm_fp16<1536, 64, 1, true, false><<<dim3(CDIM / 64, mt), 128, GEMM_SMEM(64)>>>(
                mlph, mlpl, wth + OFF_FC2 + (size_t)l * SZ_FC2, wtl + OFF_FC2 + (size_t)l * SZ_FC2,
                fc2_b + l * CDIM, h[cur], h[cur], nullptr, nullptr, M, CDIM, INV_WSCALE);
        }
    }

    head_kernel<<<BATCH, 128>>>(h[cur], norm_g, norm_b, head_w, head_b, (float*)d_out, N);
}

// round 17
// speedup vs baseline: 1.0169x; 1.0169x over previous
// THEORY (round 17): round 16's NT=96 GEMM variant REGRESSED (5673->5746):
// TN=6 accumulators + fragments exceed the 128-reg budget under
// __launch_bounds__(128,4) (spills) or 51KB smem broke 4 CTA/SM residency.
// Revert to the NT=64-only GEMM (round 15, passing at 5673); KEEP the two
// independently safe round-16 changes: flash smem overlay (Ks reuses dead Qs,
// 55KB -> 36.9KB) and wsplit packed uint2 stores (ncu: 12.3->12.0us, regs
// 28->22). Predict dur_us -> ~5600-5660, rel_err ~4.4e-6.
#include <cuda_runtime.h>
#include <cuda_fp16.h>
#include <stdint.h>
#include <stddef.h>
#include <math.h>

#define BATCH   64
#define CDIM    384
#define HEADS   6
#define MLPD    1536
#define LAYERS  12
#define NPATCH  196
#define MAXN    197
#define NCLS    100
#define EPSLN   1e-6f
#define SCALE   0.125f
#define ASTRIDE 224
#define WSCALE     64.f
#define INV_WSCALE (1.f/64.f)

#define SZ_PATCH (768*384)
#define SZ_QKV   (384*1152)
#define SZ_PROJ  (384*384)
#define SZ_FC1   (384*1536)
#define SZ_FC2   (1536*384)
#define OFF_PATCH 0
#define OFF_QKV   (SZ_PATCH)
#define OFF_PROJ  (OFF_QKV + 12*SZ_QKV)
#define OFF_FC1   (OFF_PROJ + 12*SZ_PROJ)
#define OFF_FC2   (OFF_FC1 + 12*SZ_FC1)
#define WTOTAL    (OFF_FC2 + 12*SZ_FC2)

__device__ float  g_h0[(size_t)BATCH * MAXN * CDIM];
__device__ float  g_h1[(size_t)BATCH * MAXN * CDIM];
__device__ float  g_pembed[(size_t)BATCH * NPATCH * CDIM];
__device__ int    g_idx[BATCH * NPATCH];
__device__ float  g_cls[(size_t)BATCH * HEADS * ASTRIDE];

__device__ __half g_wth[(size_t)WTOTAL];
__device__ __half g_wtl[(size_t)WTOTAL];
__device__ __half g_lnh[(size_t)BATCH * MAXN * CDIM];
__device__ __half g_lnl[(size_t)BATCH * MAXN * CDIM];
__device__ __half g_qkvh[(size_t)BATCH * MAXN * 1152];
__device__ __half g_qkvl[(size_t)BATCH * MAXN * 1152];
__device__ __half g_aoh[(size_t)BATCH * MAXN * CDIM];
__device__ __half g_aol[(size_t)BATCH * MAXN * CDIM];
__device__ __half g_mlph[(size_t)BATCH * MAXN * MLPD];
__device__ __half g_mlpl[(size_t)BATCH * MAXN * MLPD];
__device__ __half g_pxh[(size_t)BATCH * NPATCH * 768];
__device__ __half g_pxl[(size_t)BATCH * NPATCH * 768];

__device__ __forceinline__ void split_h(float v, __half& h, __half& l) {
    h = __float2half_rn(v);
    l = __float2half_rn(v - __half2float(h));
}

__device__ __forceinline__ void packsplit(float a, float b, unsigned& hi, unsigned& lo) {
    __half ah = __float2half_rn(a);
    __half al = __float2half_rn(a - __half2float(ah));
    __half bh = __float2half_rn(b);
    __half bl = __float2half_rn(b - __half2float(bh));
    hi = (unsigned)__half_as_ushort(ah) | ((unsigned)__half_as_ushort(bh) << 16);
    lo = (unsigned)__half_as_ushort(al) | ((unsigned)__half_as_ushort(bl) << 16);
}

__device__ __forceinline__ void mma16(float* c, const unsigned* a, const unsigned* b) {
    asm volatile(
        "mma.sync.aligned.m16n8k16.row.col.f32.f16.f16.f32 "
        "{%0,%1,%2,%3},{%4,%5,%6,%7},{%8,%9},{%0,%1,%2,%3};"
        : "+f"(c[0]), "+f"(c[1]), "+f"(c[2]), "+f"(c[3])
        : "r"(a[0]), "r"(a[1]), "r"(a[2]), "r"(a[3]), "r"(b[0]), "r"(b[1]));
}

__device__ __forceinline__ void ldmx4t(unsigned* r, unsigned addr) {
    asm volatile("ldmatrix.sync.aligned.m8n8.x4.trans.shared.b16 {%0,%1,%2,%3}, [%4];"
                 : "=r"(r[0]), "=r"(r[1]), "=r"(r[2]), "=r"(r[3]) : "r"(addr));
}

__device__ __forceinline__ unsigned cvta_s(const void* p) {
    unsigned a;
    asm("{ .reg .u64 t; cvta.to.shared.u64 t, %1; cvt.u32.u64 %0, t; }" : "=r"(a) : "l"(p));
    return a;
}

__device__ __forceinline__ void cp16(unsigned dst, const void* src, unsigned sz) {
    asm volatile("cp.async.cg.shared.global [%0], [%1], 16, %2;"
                 :: "r"(dst), "l"(src), "r"(sz) : "memory");
}
#define CP_COMMIT() asm volatile("cp.async.commit_group;" ::: "memory")
#define CP_WAIT0()  asm volatile("cp.async.wait_group 0;" ::: "memory")

// ------- fp16x3 GEMM, 64x64x32 tile, 128 thr, 4 CTAs/SM, single-sync pipeline -------
#define GEMM_SMEM 40960

__device__ __forceinline__ void gemm_issue(
    unsigned sb, const __half* Ah, const __half* Al,
    const __half* Bth, const __half* Btl,
    int M, int K, int m0, int n0, int t, int c) {
    int p = c & 1;
    int kb = c * 32;
#pragma unroll
    for (int s = 0; s < 2; s++) {
        const __half* asrc = s ? Al : Ah;
#pragma unroll
        for (int it = 0; it < 2; it++) {
            int idx = t + it * 128;
            int row = idx >> 2, c4 = idx & 3;
            int gm = m0 + row;
            int gmc = (gm < M) ? gm : (M - 1);
            const __half* src = asrc + (size_t)gmc * K + kb + 8 * c4;
            unsigned dst = sb + (unsigned)(p * 5120 + s * 2560 + row * 40 + 8 * c4) * 2u;
            cp16(dst, src, (gm < M) ? 16u : 0u);
        }
        const __half* bsrc = s ? Btl : Bth;
#pragma unroll
        for (int it = 0; it < 2; it++) {
            int idx = t + it * 128;
            int brow = idx >> 2, bc4 = idx & 3;
            const __half* srcb = bsrc + (size_t)(n0 + brow) * K + kb + 8 * bc4;
            unsigned dstb = sb + (unsigned)(10240 + p * 5120 + s * 2560 + brow * 40 + 8 * bc4) * 2u;
            cp16(dstb, srcb, 16u);
        }
    }
    CP_COMMIT();
}

template<int KT, int EPI, bool OF32, bool OHALF>
__global__ __launch_bounds__(128, 4)
void gemm_fp16(const __half* __restrict__ Ah, const __half* __restrict__ Al,
               const __half* __restrict__ Bth, const __half* __restrict__ Btl,
               const float* __restrict__ bias, const float* __restrict__ res,
               float* __restrict__ C32, __half* __restrict__ Ch, __half* __restrict__ Cl,
               int M, int Nout, float oscale) {
    extern __shared__ __half smp[];
    unsigned sb = cvta_s(smp);
    int t = threadIdx.x, lane = t & 31, wid = t >> 5;
    int g = lane >> 2, q = lane & 3;
    int wm = wid >> 1, wn = wid & 1;
    int m0 = blockIdx.y * 64, n0 = blockIdx.x * 64;
    float acc[2][4][4] = {};
    const int nch = KT >> 5;

    gemm_issue(sb, Ah, Al, Bth, Btl, M, KT, m0, n0, t, 0);
#pragma unroll 2
    for (int c = 0; c < nch; c++) {
        CP_WAIT0();
        __syncthreads();
        if (c + 1 < nch) gemm_issue(sb, Ah, Al, Bth, Btl, M, KT, m0, n0, t, c + 1);
        int p = c & 1;
        const __half* Ab = smp + p * 5120;
        const __half* Bb = smp + 10240 + p * 5120;
#pragma unroll
        for (int ks = 0; ks < 2; ks++) {
            int kb = ks * 16;
            unsigned aH[2][4], aL[2][4];
#pragma unroll
            for (int tm = 0; tm < 2; tm++) {
                int r0 = wm * 32 + tm * 16;
                const __half* a0 = Ab + (r0 + g) * 40;
                const __half* a8 = Ab + (r0 + g + 8) * 40;
                aH[tm][0] = *(const unsigned*)(a0 + kb + 2 * q);
                aH[tm][1] = *(const unsigned*)(a8 + kb + 2 * q);
                aH[tm][2] = *(const unsigned*)(a0 + kb + 2 * q + 8);
                aH[tm][3] = *(const unsigned*)(a8 + kb + 2 * q + 8);
                const __half* l0 = a0 + 2560;
                const __half* l8 = a8 + 2560;
                aL[tm][0] = *(const unsigned*)(l0 + kb + 2 * q);
                aL[tm][1] = *(const unsigned*)(l8 + kb + 2 * q);
                aL[tm][2] = *(const unsigned*)(l0 + kb + 2 * q + 8);
                aL[tm][3] = *(const unsigned*)(l8 + kb + 2 * q + 8);
            }
            unsigned bH[4][2], bL[4][2];
#pragma unroll
            for (int tn = 0; tn < 4; tn++) {
                int n = wn * 32 + tn * 8 + g;
                const __half* b0 = Bb + n * 40;
                bH[tn][0] = *(const unsigned*)(b0 + kb + 2 * q);
                bH[tn][1] = *(const unsigned*)(b0 + kb + 2 * q + 8);
                const __half* bl = b0 + 2560;
                bL[tn][0] = *(const unsigned*)(bl + kb + 2 * q);
                bL[tn][1] = *(const unsigned*)(bl + kb + 2 * q + 8);
            }
#pragma unroll
            for (int tm = 0; tm < 2; tm++)
#pragma unroll
                for (int tn = 0; tn < 4; tn++) {
                    mma16(acc[tm][tn], aH[tm], bH[tn]);
                    mma16(acc[tm][tn], aH[tm], bL[tn]);
                    mma16(acc[tm][tn], aL[tm], bH[tn]);
                }
        }
    }

#pragma unroll
    for (int tm = 0; tm < 2; tm++) {
#pragma unroll
        for (int tn = 0; tn < 4; tn++) {
            int col = n0 + wn * 32 + tn * 8 + 2 * q;
            int r0 = m0 + wm * 32 + tm * 16;
            float2 bv = *(const float2*)&bias[col];
#pragma unroll
            for (int hf = 0; hf < 2; hf++) {
                int gm = r0 + g + 8 * hf;
                if (gm >= M) continue;
                float v0 = acc[tm][tn][hf * 2]     * oscale + bv.x;
                float v1 = acc[tm][tn][hf * 2 + 1] * oscale + bv.y;
                if (EPI == 1) {
                    float2 rv = *(const float2*)&res[(size_t)gm * Nout + col];
                    v0 += rv.x; v1 += rv.y;
                }
                if (EPI == 2) {
                    v0 = 0.5f * v0 * (1.f + erff(v0 * 0.70710678118654752f));
                    v1 = 0.5f * v1 * (1.f + erff(v1 * 0.70710678118654752f));
                }
                if (OF32) *(float2*)&C32[(size_t)gm * Nout + col] = make_float2(v0, v1);
                if (OHALF) {
                    unsigned ph2, pl2;
                    packsplit(v0, v1, ph2, pl2);
                    *(unsigned*)&Ch[(size_t)gm * Nout + col] = ph2;
                    *(unsigned*)&Cl[(size_t)gm * Nout + col] = pl2;
                }
            }
        }
    }
}

// ---------------- weight transpose + split (packed uint2 stores) ----------------
__global__ void wsplit_kernel(const float* __restrict__ W, size_t in_lstride,
                              __half* __restrict__ oh, __half* __restrict__ ol,
                              size_t out_lstride, int K, int N) {
    __shared__ float tile[32][33];
    int k0 = blockIdx.x * 32, n0 = blockIdx.y * 32;
    const float* Wl = W + (size_t)blockIdx.z * in_lstride;
    __half* ohl = oh + (size_t)blockIdx.z * out_lstride;
    __half* oll = ol + (size_t)blockIdx.z * out_lstride;
    int tx = threadIdx.x, ty = threadIdx.y;
#pragma unroll
    for (int i = 0; i < 4; i++)
        tile[ty + 8 * i][tx] = Wl[(size_t)(k0 + ty + 8 * i) * N + n0 + tx];
    __syncthreads();
    int t = ty * 32 + tx;
    int nl = t >> 3, kq = t & 7;
    float v0 = tile[4 * kq][nl]     * WSCALE;
    float v1 = tile[4 * kq + 1][nl] * WSCALE;
    float v2 = tile[4 * kq + 2][nl] * WSCALE;
    float v3 = tile[4 * kq + 3][nl] * WSCALE;
    unsigned h01, l01, h23, l23;
    packsplit(v0, v1, h01, l01);
    packsplit(v2, v3, h23, l23);
    size_t o = (size_t)(n0 + nl) * K + k0 + 4 * kq;
    *(uint2*)&ohl[o] = make_uint2(h01, h23);
    *(uint2*)&oll[o] = make_uint2(l01, l23);
}

// ---------------- patchify + split ----------------
__global__ void patchify_kernel(const float* __restrict__ x,
                                __half* __restrict__ ph, __half* __restrict__ pl) {
    int i = blockIdx.x * 256 + threadIdx.x;
    const int TOT = BATCH * NPATCH * 768;
    if (i >= TOT) return;
    int k  = i % 768;
    int tt = (i / 768) % NPATCH;
    int b  = i / (768 * NPATCH);
    int ch = k >> 8, py = (k >> 4) & 15, px = k & 15;
    int gy = tt / 14, gx = tt % 14;
    float v = x[(((size_t)b * 3 + ch) * 224 + gy * 16 + py) * 224 + gx * 16 + px];
    split_h(v, ph[i], pl[i]);
}

// ---------------- assemble ----------------
__global__ void assemble_kernel(const float* __restrict__ pe, const float* __restrict__ cls,
                                const float* __restrict__ pos, float* __restrict__ h) {
    int i = blockIdx.x * 256 + threadIdx.x;
    const int TOT = BATCH * MAXN * CDIM;
    if (i >= TOT) return;
    int c = i % CDIM;
    int r = (i / CDIM) % MAXN;
    int b = i / (CDIM * MAXN);
    float v = (r == 0) ? cls[c] : pe[((size_t)b * NPATCH + (r - 1)) * CDIM + c];
    h[i] = v + pos[r * CDIM + c];
}

// ---------------- LayerNorm: warp-per-row ----------------
__global__ __launch_bounds__(128)
void ln_kernel(const float* __restrict__ x, const float* __restrict__ g,
               const float* __restrict__ bb, __half* __restrict__ yh, __half* __restrict__ yl,
               int rows) {
    int row = blockIdx.x * 4 + (threadIdx.x >> 5);
    if (row >= rows) return;
    int lane = threadIdx.x & 31;
    const float4* xr = (const float4*)(x + (size_t)row * CDIM);
    float4 v[3];
    float s = 0.f, s2 = 0.f;
#pragma unroll
    for (int l = 0; l < 3; l++) {
        v[l] = xr[lane + 32 * l];
        s  += v[l].x + v[l].y + v[l].z + v[l].w;
        s2 += v[l].x * v[l].x + v[l].y * v[l].y + v[l].z * v[l].z + v[l].w * v[l].w;
    }
#pragma unroll
    for (int o = 16; o; o >>= 1) {
        s  += __shfl_xor_sync(~0u, s, o);
        s2 += __shfl_xor_sync(~0u, s2, o);
    }
    float mean = s * (1.f / CDIM);
    float var  = s2 * (1.f / CDIM) - mean * mean;
    float r = rsqrtf(var + EPSLN);
#pragma unroll
    for (int l = 0; l < 3; l++) {
        int c4 = lane + 32 * l;
        float4 gv = *(const float4*)(g + 4 * c4);
        float4 bv = *(const float4*)(bb + 4 * c4);
        float o0 = (v[l].x - mean) * r * gv.x + bv.x;
        float o1 = (v[l].y - mean) * r * gv.y + bv.y;
        float o2 = (v[l].z - mean) * r * gv.z + bv.z;
        float o3 = (v[l].w - mean) * r * gv.w + bv.w;
        unsigned h01, l01, h23, l23;
        packsplit(o0, o1, h01, l01);
        packsplit(o2, o3, h23, l23);
        *(uint2*)&yh[(size_t)row * CDIM + 4 * c4] = make_uint2(h01, h23);
        *(uint2*)&yl[(size_t)row * CDIM + 4 * c4] = make_uint2(l01, l23);
    }
}

// ---------------- fused flash attention (smem overlay: Ks reuses Qs) ----------------
#define FLASH_SMEM 36864

__global__ __launch_bounds__(128)
void flash_attn(const __half* __restrict__ qkvh, const __half* __restrict__ qkvl,
                __half* __restrict__ aoh, __half* __restrict__ aol,
                float* __restrict__ clslog, int N) {
    extern __shared__ __half fsm[];
    __half* Qs = fsm;            // prologue only
    __half* Ks = fsm;            // overlays Qs after fragment hoist
    __half* Vs = fsm + 9216;
    int bh = blockIdx.y;
    int b = bh / HEADS, hh = bh % HEADS;
    int i0 = blockIdx.x * 64;
    int t = threadIdx.x, lane = t & 31, wid = t >> 5;
    int g = lane >> 2, q = lane & 3;
    const uint4 z4 = make_uint4(0, 0, 0, 0);
    unsigned vs_addr = cvta_s(fsm) + 9216u * 2u;

#pragma unroll
    for (int s = 0; s < 2; s++) {
        const __half* src = s ? qkvl : qkvh;
#pragma unroll
        for (int it = 0; it < 4; it++) {
            int idx = t + it * 128;
            int row = idx >> 3, c = idx & 7;
            int gi = i0 + row;
            uint4 v = z4;
            if (gi < N) v = *(const uint4*)&src[((size_t)b * N + gi) * 1152 + hh * 64 + 8 * c];
            *(uint4*)&Qs[s * 4608 + row * 72 + 8 * c] = v;
        }
    }
    __syncthreads();

    unsigned qH[4][4], qL[4][4];
#pragma unroll
    for (int ks = 0; ks < 4; ks++) {
        int kb = ks * 16;
        const __half* a0 = Qs + (wid * 16 + g) * 72;
        const __half* a8 = Qs + (wid * 16 + g + 8) * 72;
        qH[ks][0] = *(const unsigned*)(a0 + kb + 2 * q);
        qH[ks][1] = *(const unsigned*)(a8 + kb + 2 * q);
        qH[ks][2] = *(const unsigned*)(a0 + kb + 2 * q + 8);
        qH[ks][3] = *(const unsigned*)(a8 + kb + 2 * q + 8);
        qL[ks][0] = *(const unsigned*)(a0 + 4608 + kb + 2 * q);
        qL[ks][1] = *(const unsigned*)(a8 + 4608 + kb + 2 * q);
        qL[ks][2] = *(const unsigned*)(a0 + 4608 + kb + 2 * q + 8);
        qL[ks][3] = *(const unsigned*)(a8 + 4608 + kb + 2 * q + 8);
    }

    float m_lo = -1e30f, m_hi = -1e30f, s_lo = 0.f, s_hi = 0.f;
    float acc_o[8][4] = {};
    int ntj = (N + 63) >> 6;

    unsigned vrow_in_tile = (unsigned)(lane & 15);
    unsigned vcol8 = (lane & 16) ? 8u : 0u;

    for (int jt = 0; jt < ntj; jt++) {
        int j0 = jt * 64;
        int tnm = (N - j0 + 7) >> 3;  if (tnm > 8) tnm = 8;
        int ksm = (N - j0 + 15) >> 4; if (ksm > 4) ksm = 4;
        __syncthreads();
#pragma unroll
        for (int s = 0; s < 2; s++) {
            const __half* src = s ? qkvl : qkvh;
#pragma unroll
            for (int it = 0; it < 4; it++) {
                int idx = t + it * 128;
                int row = idx >> 3, c = idx & 7;
                int gj = j0 + row;
                uint4 vk = z4, vv = z4;
                if (gj < N) {
                    size_t base = ((size_t)b * N + gj) * 1152 + hh * 64 + 8 * c;
                    vk = *(const uint4*)&src[base + 384];
                    vv = *(const uint4*)&src[base + 768];
                }
                *(uint4*)&Ks[s * 4608 + row * 72 + 8 * c] = vk;
                *(uint4*)&Vs[s * 4608 + row * 72 + 8 * c] = vv;
            }
        }
        __syncthreads();

        float sa[8][4] = {};
#pragma unroll
        for (int ks = 0; ks < 4; ks++) {
            int kb = ks * 16;
            for (int tn = 0; tn < tnm; tn++) {
                unsigned bHf[2], bLf[2];
                const __half* b0 = Ks + (tn * 8 + g) * 72;
                bHf[0] = *(const unsigned*)(b0 + kb + 2 * q);
                bHf[1] = *(const unsigned*)(b0 + kb + 2 * q + 8);
                bLf[0] = *(const unsigned*)(b0 + 4608 + kb + 2 * q);
                bLf[1] = *(const unsigned*)(b0 + 4608 + kb + 2 * q + 8);
                mma16(sa[tn], qH[ks], bHf);
                mma16(sa[tn], qH[ks], bLf);
                mma16(sa[tn], qL[ks], bHf);
            }
        }

#pragma unroll
        for (int tn = 0; tn < 8; tn++) {
#pragma unroll
            for (int r = 0; r < 4; r++) {
                int col = j0 + tn * 8 + 2 * q + (r & 1);
                float v = sa[tn][r] * SCALE;
                sa[tn][r] = (col < N) ? v : -1e30f;
            }
        }
        if (blockIdx.x == 0 && wid == 0 && g == 0) {
#pragma unroll
            for (int tn = 0; tn < 8; tn++) {
#pragma unroll
                for (int r = 0; r < 2; r++) {
                    int col = j0 + tn * 8 + 2 * q + r;
                    if (col < ASTRIDE) clslog[(size_t)bh * ASTRIDE + col] = sa[tn][r];
                }
            }
        }

        float mt_lo = -1e30f, mt_hi = -1e30f;
#pragma unroll
        for (int tn = 0; tn < 8; tn++) {
            mt_lo = fmaxf(mt_lo, fmaxf(sa[tn][0], sa[tn][1]));
            mt_hi = fmaxf(mt_hi, fmaxf(sa[tn][2], sa[tn][3]));
        }
        mt_lo = fmaxf(mt_lo, __shfl_xor_sync(~0u, mt_lo, 1));
        mt_lo = fmaxf(mt_lo, __shfl_xor_sync(~0u, mt_lo, 2));
        mt_hi = fmaxf(mt_hi, __shfl_xor_sync(~0u, mt_hi, 1));
        mt_hi = fmaxf(mt_hi, __shfl_xor_sync(~0u, mt_hi, 2));
        float mn_lo = fmaxf(m_lo, mt_lo), mn_hi = fmaxf(m_hi, mt_hi);
        float al_lo = expf(m_lo - mn_lo), al_hi = expf(m_hi - mn_hi);
        m_lo = mn_lo; m_hi = mn_hi;
        float ts_lo = 0.f, ts_hi = 0.f;
#pragma unroll
        for (int tn = 0; tn < 8; tn++) {
            sa[tn][0] = expf(sa[tn][0] - m_lo) * 256.f;
            sa[tn][1] = expf(sa[tn][1] - m_lo) * 256.f;
            sa[tn][2] = expf(sa[tn][2] - m_hi) * 256.f;
            sa[tn][3] = expf(sa[tn][3] - m_hi) * 256.f;
            ts_lo += sa[tn][0] + sa[tn][1];
            ts_hi += sa[tn][2] + sa[tn][3];
        }
        ts_lo += __shfl_xor_sync(~0u, ts_lo, 1);
        ts_lo += __shfl_xor_sync(~0u, ts_lo, 2);
        ts_hi += __shfl_xor_sync(~0u, ts_hi, 1);
        ts_hi += __shfl_xor_sync(~0u, ts_hi, 2);
        s_lo = s_lo * al_lo + ts_lo;
        s_hi = s_hi * al_hi + ts_hi;
#pragma unroll
        for (int tn = 0; tn < 8; tn++) {
            acc_o[tn][0] *= al_lo; acc_o[tn][1] *= al_lo;
            acc_o[tn][2] *= al_hi; acc_o[tn][3] *= al_hi;
        }

        for (int ks = 0; ks < ksm; ks++) {
            unsigned aH[4], aL[4];
            packsplit(sa[2 * ks][0],     sa[2 * ks][1],     aH[0], aL[0]);
            packsplit(sa[2 * ks][2],     sa[2 * ks][3],     aH[1], aL[1]);
            packsplit(sa[2 * ks + 1][0], sa[2 * ks + 1][1], aH[2], aL[2]);
            packsplit(sa[2 * ks + 1][2], sa[2 * ks + 1][3], aH[3], aL[3]);
            unsigned rowbase = (unsigned)(ks * 16) + vrow_in_tile;
#pragma unroll
            for (int ng = 0; ng < 4; ng++) {
                unsigned addrH = vs_addr + (rowbase * 72u + (unsigned)(ng * 16) + vcol8) * 2u;
                unsigned bh4[4], bl4[4];
                ldmx4t(bh4, addrH);
                ldmx4t(bl4, addrH + 4608u * 2u);
                mma16(acc_o[2 * ng],     aH, &bh4[0]);
                mma16(acc_o[2 * ng],     aH, &bl4[0]);
                mma16(acc_o[2 * ng],     aL, &bh4[0]);
                mma16(acc_o[2 * ng + 1], aH, &bh4[2]);
                mma16(acc_o[2 * ng + 1], aH, &bl4[2]);
                mma16(acc_o[2 * ng + 1], aL, &bh4[2]);
            }
        }
    }

    float inv_lo = 1.f / fmaxf(s_lo, 1e-30f);
    float inv_hi = 1.f / fmaxf(s_hi, 1e-30f);
#pragma unroll
    for (int tn = 0; tn < 8; tn++) {
#pragma unroll
        for (int r = 0; r < 4; r++) {
            int gi = i0 + wid * 16 + g + ((r >= 2) ? 8 : 0);
            if (gi >= N) continue;
            int d = tn * 8 + 2 * q + (r & 1);
            float v = acc_o[tn][r] * ((r < 2) ? inv_lo : inv_hi);
            __half hh2, ll2;
            split_h(v, hh2, ll2);
            size_t oo = ((size_t)b * N + gi) * CDIM + hh * 64 + d;
            aoh[oo] = hh2;
            aol[oo] = ll2;
        }
    }
}

// ---------------- merged prune kernel ----------------
__global__ __launch_bounds__(256)
void prune_kernel(const float* __restrict__ cls, int* __restrict__ idxout, int N, int keep) {
    int b = blockIdx.x;
    int t = threadIdx.x;
    __shared__ float sc[256];
    __shared__ float red[8];
    int Ntok = N - 1;
    sc[t] = 0.f;
    __syncthreads();
    for (int hh = 0; hh < HEADS; hh++) {
        const float* r = cls + (size_t)(b * HEADS + hh) * ASTRIDE;
        float mx = -1e30f;
        for (int j = t; j < N; j += 256) mx = fmaxf(mx, r[j]);
#pragma unroll
        for (int o = 16; o; o >>= 1) mx = fmaxf(mx, __shfl_xor_sync(~0u, mx, o));
        if ((t & 31) == 0) red[t >> 5] = mx;
        __syncthreads();
        mx = red[0];
#pragma unroll
        for (int w = 1; w < 8; w++) mx = fmaxf(mx, red[w]);
        __syncthreads();
        float sum = 0.f;
        for (int j = t; j < N; j += 256) sum += expf(r[j] - mx);
#pragma unroll
        for (int o = 16; o; o >>= 1) sum += __shfl_xor_sync(~0u, sum, o);
        if ((t & 31) == 0) red[t >> 5] = sum;
        __syncthreads();
        sum = 0.f;
#pragma unroll
        for (int w = 0; w < 8; w++) sum += red[w];
        float inv = 1.f / sum;
        for (int j = t; j < Ntok; j += 256) sc[j] += expf(r[1 + j] - mx) * inv;
        __syncthreads();
    }
    if (t < Ntok) {
        float mine = sc[t];
        int rk = 0;
        for (int j = 0; j < Ntok; j++)
            rk += (sc[j] > mine) || (sc[j] == mine && j < t);
        if (rk < keep) idxout[b * keep + rk] = t;
    }
}

__global__ void gather_kernel(const float* __restrict__ src, float* __restrict__ dst,
                              const int* __restrict__ idx, int N, int keep) {
    int newN = keep + 1;
    size_t TOT = (size_t)BATCH * newN * CDIM;
    size_t i = (size_t)blockIdx.x * 256 + threadIdx.x;
    if (i >= TOT) return;
    int c = i % CDIM;
    int r = (i / CDIM) % newN;
    int b = i / ((size_t)CDIM * newN);
    int sr = (r == 0) ? 0 : 1 + idx[b * keep + r - 1];
    dst[i] = src[((size_t)b * N + sr) * CDIM + c];
}

// ---------------- fused final LN + head ----------------
__global__ __launch_bounds__(128)
void head_kernel(const float* __restrict__ h, const float* __restrict__ g,
                 const float* __restrict__ bb, const float* __restrict__ W,
                 const float* __restrict__ wb, float* __restrict__ out, int N) {
    int b = blockIdx.x;
    const float* xr = h + (size_t)(b * N) * CDIM;
    __shared__ float sm[CDIM];
    int t = threadIdx.x;
    float v[3];
    float s = 0.f, s2 = 0.f;
#pragma unroll
    for (int l = 0; l < 3; l++) { v[l] = xr[t + 128 * l]; s += v[l]; s2 += v[l] * v[l]; }
#pragma unroll
    for (int o = 16; o; o >>= 1) {
        s  += __shfl_xor_sync(~0u, s, o);
        s2 += __shfl_xor_sync(~0u, s2, o);
    }
    __shared__ float ws[4], ws2[4];
    if ((t & 31) == 0) { ws[t >> 5] = s; ws2[t >> 5] = s2; }
    __syncthreads();
    s  = ws[0] + ws[1] + ws[2] + ws[3];
    s2 = ws2[0] + ws2[1] + ws2[2] + ws2[3];
    float mean = s * (1.f / CDIM);
    float var  = s2 * (1.f / CDIM) - mean * mean;
    float r = rsqrtf(var + EPSLN);
#pragma unroll
    for (int l = 0; l < 3; l++) {
        int c = t + 128 * l;
        sm[c] = (v[l] - mean) * r * g[c] + bb[c];
    }
    __syncthreads();
    if (t < NCLS) {
        float acc = wb[t];
        for (int k = 0; k < CDIM; k++)
            acc += sm[k] * W[k * NCLS + t];
        out[b * NCLS + t] = acc;
    }
}

// ---------------- launch ----------------
extern "C" void kernel_launch(void* const* d_in, const int* in_sizes, int n_in,
                              void* d_out, int out_size) {
    const float* x        = (const float*)d_in[0];
    const float* patch_w  = (const float*)d_in[1];
    const float* patch_b  = (const float*)d_in[2];
    const float* cls_tok  = (const float*)d_in[3];
    const float* pos_emb  = (const float*)d_in[4];
    const float* ln1_g    = (const float*)d_in[5];
    const float* ln1_b    = (const float*)d_in[6];
    const float* qkv_w    = (const float*)d_in[7];
    const float* qkv_b    = (const float*)d_in[8];
    const float* proj_w   = (const float*)d_in[9];
    const float* proj_b   = (const float*)d_in[10];
    const float* ln2_g    = (const float*)d_in[11];
    const float* ln2_b    = (const float*)d_in[12];
    const float* fc1_w    = (const float*)d_in[13];
    const float* fc1_b    = (const float*)d_in[14];
    const float* fc2_w    = (const float*)d_in[15];
    const float* fc2_b    = (const float*)d_in[16];
    const float* norm_g   = (const float*)d_in[17];
    const float* norm_b   = (const float*)d_in[18];
    const float* head_w   = (const float*)d_in[19];
    const float* head_b   = (const float*)d_in[20];

    float *h[2], *pembed, *clsb;
    int* idxb;
    __half *wth, *wtl, *lnh, *lnl, *qkvh, *qkvl, *aoh, *aol, *mlph, *mlpl, *pxh, *pxl;
    cudaGetSymbolAddress((void**)&h[0], g_h0);
    cudaGetSymbolAddress((void**)&h[1], g_h1);
    cudaGetSymbolAddress((void**)&pembed, g_pembed);
    cudaGetSymbolAddress((void**)&idxb, g_idx);
    cudaGetSymbolAddress((void**)&clsb, g_cls);
    cudaGetSymbolAddress((void**)&wth, g_wth);
    cudaGetSymbolAddress((void**)&wtl, g_wtl);
    cudaGetSymbolAddress((void**)&lnh, g_lnh);
    cudaGetSymbolAddress((void**)&lnl, g_lnl);
    cudaGetSymbolAddress((void**)&qkvh, g_qkvh);
    cudaGetSymbolAddress((void**)&qkvl, g_qkvl);
    cudaGetSymbolAddress((void**)&aoh, g_aoh);
    cudaGetSymbolAddress((void**)&aol, g_aol);
    cudaGetSymbolAddress((void**)&mlph, g_mlph);
    cudaGetSymbolAddress((void**)&mlpl, g_mlpl);
    cudaGetSymbolAddress((void**)&pxh, g_pxh);
    cudaGetSymbolAddress((void**)&pxl, g_pxl);

    cudaFuncSetAttribute(gemm_fp16<768,  0, true,  false>, cudaFuncAttributeMaxDynamicSharedMemorySize, GEMM_SMEM);
    cudaFuncSetAttribute(gemm_fp16<384,  0, false, true >, cudaFuncAttributeMaxDynamicSharedMemorySize, GEMM_SMEM);
    cudaFuncSetAttribute(gemm_fp16<384,  1, true,  false>, cudaFuncAttributeMaxDynamicSharedMemorySize, GEMM_SMEM);
    cudaFuncSetAttribute(gemm_fp16<384,  2, false, true >, cudaFuncAttributeMaxDynamicSharedMemorySize, GEMM_SMEM);
    cudaFuncSetAttribute(gemm_fp16<1536, 1, true,  false>, cudaFuncAttributeMaxDynamicSharedMemorySize, GEMM_SMEM);
    cudaFuncSetAttribute(flash_attn, cudaFuncAttributeMaxDynamicSharedMemorySize, FLASH_SMEM);

    {
        dim3 blk(32, 8);
        wsplit_kernel<<<dim3(768 / 32, 384 / 32, 1), blk>>>(patch_w, 0, wth + OFF_PATCH, wtl + OFF_PATCH, 0, 768, 384);
        wsplit_kernel<<<dim3(384 / 32, 1152 / 32, 12), blk>>>(qkv_w, (size_t)384 * 1152, wth + OFF_QKV, wtl + OFF_QKV, SZ_QKV, 384, 1152);
        wsplit_kernel<<<dim3(384 / 32, 384 / 32, 12), blk>>>(proj_w, (size_t)384 * 384, wth + OFF_PROJ, wtl + OFF_PROJ, SZ_PROJ, 384, 384);
        wsplit_kernel<<<dim3(384 / 32, 1536 / 32, 12), blk>>>(fc1_w, (size_t)384 * 1536, wth + OFF_FC1, wtl + OFF_FC1, SZ_FC1, 384, 1536);
        wsplit_kernel<<<dim3(1536 / 32, 384 / 32, 12), blk>>>(fc2_w, (size_t)1536 * 384, wth + OFF_FC2, wtl + OFF_FC2, SZ_FC2, 1536, 384);
    }

    {
        int tot = BATCH * NPATCH * 768;
        patchify_kernel<<<(tot + 255) / 256, 256>>>(x, pxh, pxl);
        int M = BATCH * NPATCH;
        gemm_fp16<768, 0, true, false><<<dim3(CDIM / 64, (M + 63) / 64), 128, GEMM_SMEM>>>(
            pxh, pxl, wth + OFF_PATCH, wtl + OFF_PATCH, patch_b, nullptr,
            pembed, nullptr, nullptr, M, CDIM, INV_WSCALE);
        int tot2 = BATCH * MAXN * CDIM;
        assemble_kernel<<<(tot2 + 255) / 256, 256>>>(pembed, cls_tok, pos_emb, h[0]);
    }

    int cur = 0;
    int N = MAXN;
    for (int l = 0; l < LAYERS; l++) {
        int M = BATCH * N;
        ln_kernel<<<(M + 3) / 4, 128>>>(h[cur], ln1_g + l * CDIM, ln1_b + l * CDIM, lnh, lnl, M);
        gemm_fp16<384, 0, false, true><<<dim3(1152 / 64, (M + 63) / 64), 128, GEMM_SMEM>>>(
            lnh, lnl, wth + OFF_QKV + (size_t)l * SZ_QKV, wtl + OFF_QKV + (size_t)l * SZ_QKV,
            qkv_b + l * 1152, nullptr, nullptr, qkvh, qkvl, M, 1152, INV_WSCALE);
        int nt = (N + 63) / 64;
        flash_attn<<<dim3(nt, BATCH * HEADS), 128, FLASH_SMEM>>>(qkvh, qkvl, aoh, aol, clsb, N);
        gemm_fp16<384, 1, true, false><<<dim3(CDIM / 64, (M + 63) / 64), 128, GEMM_SMEM>>>(
            aoh, aol, wth + OFF_PROJ + (size_t)l * SZ_PROJ, wtl + OFF_PROJ + (size_t)l * SZ_PROJ,
            proj_b + l * CDIM, h[cur], h[cur], nullptr, nullptr, M, CDIM, INV_WSCALE);
        if (l == 2 || l == 4 || l == 6) {
            int keep = (l == 2) ? 176 : (l == 4) ? 149 : 119;
            prune_kernel<<<BATCH, 256>>>(clsb, idxb, N, keep);
            int newN = keep + 1;
            size_t tot = (size_t)BATCH * newN * CDIM;
            gather_kernel<<<(int)((tot + 255) / 256), 256>>>(h[cur], h[1 - cur], idxb, N, keep);
            cur ^= 1;
            N = newN;
            M = BATCH * N;
        }
        ln_kernel<<<(M + 3) / 4, 128>>>(h[cur], ln2_g + l * CDIM, ln2_b + l * CDIM, lnh, lnl, M);
        gemm_fp16<384, 2, false, true><<<dim3(MLPD / 64, (M + 63) / 64), 128, GEMM_SMEM>>>(
            lnh, lnl, wth + OFF_FC1 + (size_t)l * SZ_FC1, wtl + OFF_FC1 + (size_t)l * SZ_FC1,
            fc1_b + l * MLPD, nullptr, nullptr, mlph, mlpl, M, MLPD, INV_WSCALE);
        gemm_fp16<1536, 1, true, false><<<dim3(CDIM / 64, (M + 63) / 64), 128, GEMM_SMEM>>>(
            mlph, mlpl, wth + OFF_FC2 + (size_t)l * SZ_FC2, wtl + OFF_FC2 + (size_t)l * SZ_FC2,
            fc2_b + l * CDIM, h[cur], h[cur], nullptr, nullptr, M, CDIM, INV_WSCALE);
    }

    head_kernel<<<BATCH, 128>>>(h[cur], norm_g, norm_b, head_w, head_b, (float*)d_out, N);
}